// round 2
// baseline (speedup 1.0000x reference)
#include <cuda_runtime.h>
#include <math_constants.h>

#define B_ 4
#define C_ 128
#define N_ 4096

// Scratch: q,k channel-major [B][C][N]; v row-major [B][N][C]
__device__ float g_q[B_ * C_ * N_];
__device__ float g_k[B_ * C_ * N_];
__device__ float g_v[B_ * N_ * C_];

// ---------------------------------------------------------------------------
// QKV projection: out[o][n] = sum_c w[o][c] * x[c][n] + bias[o]
// grid: (N/64, 6, B)   otile 0,1 -> q ; 2,3 -> k ; 4,5 -> v
// block: 256 (16x16), each thread computes 4o x 4n
// smem: Xs[128][64] (c-major), Ws[64][128] (o-major)  = 64 KB dynamic
// ---------------------------------------------------------------------------
__global__ __launch_bounds__(256) void qkv_kernel(
    const float* __restrict__ x,
    const float* __restrict__ wq, const float* __restrict__ bq,
    const float* __restrict__ wk, const float* __restrict__ bk,
    const float* __restrict__ wv, const float* __restrict__ bv)
{
    extern __shared__ float sm[];
    float* Xs = sm;          // 128*64
    float* Ws = sm + 8192;   // 64*128

    const int tid = threadIdx.x;
    const int tx = tid & 15, ty = tid >> 4;
    const int ntile = blockIdx.x, otile = blockIdx.y, b = blockIdx.z;

    const float* w;
    const float* bias;
    if (otile < 2)      { w = wq; bias = bq; }
    else if (otile < 4) { w = wk; bias = bk; }
    else                { w = wv; bias = bv; }
    const int orow0 = (otile & 1) * 64;
    const int n0 = ntile * 64;

    #pragma unroll
    for (int p = 0; p < 32; p++) {
        int idx = tid + p * 256;
        int o = idx >> 7, c = idx & 127;
        Ws[idx] = w[(orow0 + o) * C_ + c];
    }
    #pragma unroll
    for (int p = 0; p < 32; p++) {
        int idx = tid + p * 256;
        int c = idx >> 6, nn = idx & 63;
        Xs[idx] = x[(b * C_ + c) * N_ + n0 + nn];
    }
    __syncthreads();

    float acc[4][4];
    #pragma unroll
    for (int i = 0; i < 4; i++)
        #pragma unroll
        for (int j = 0; j < 4; j++) acc[i][j] = 0.f;

    #pragma unroll 8
    for (int c = 0; c < 128; c++) {
        float4 xf = *(const float4*)&Xs[c * 64 + tx * 4];
        #pragma unroll
        for (int i = 0; i < 4; i++) {
            float wf = Ws[(ty * 4 + i) * 128 + c];
            acc[i][0] += wf * xf.x;
            acc[i][1] += wf * xf.y;
            acc[i][2] += wf * xf.z;
            acc[i][3] += wf * xf.w;
        }
    }

    float bb[4];
    #pragma unroll
    for (int i = 0; i < 4; i++) bb[i] = bias[orow0 + ty * 4 + i];

    if (otile < 4) {
        // q/k: channel-major [B][C][N], float4 contiguous along n
        float* out = (otile < 2) ? g_q : g_k;
        #pragma unroll
        for (int i = 0; i < 4; i++) {
            int oc = orow0 + ty * 4 + i;
            float4 r = make_float4(acc[i][0] + bb[i], acc[i][1] + bb[i],
                                   acc[i][2] + bb[i], acc[i][3] + bb[i]);
            *(float4*)&out[(b * C_ + oc) * N_ + n0 + tx * 4] = r;
        }
    } else {
        // v: row-major [B][N][C], float4 contiguous along channel
        #pragma unroll
        for (int j = 0; j < 4; j++) {
            int n = n0 + tx * 4 + j;
            float4 r = make_float4(acc[0][j] + bb[0], acc[1][j] + bb[1],
                                   acc[2][j] + bb[2], acc[3][j] + bb[3]);
            *(float4*)&g_v[(b * N_ + n) * C_ + orow0 + ty * 4] = r;
        }
    }
}

// ---------------------------------------------------------------------------
// Flash attention: grid (N/64, B), block 256 (16x16)
// Q tile resident (64q x 128c), stream 64-key K/V tiles.
// Thread (tx,ty): scores s[4 rows(ty)][4 cols(tx)], O[4 rows][8 ch(tx)]
// smem: Qs[128][64] + Ks[128][64] + Vs[64][128] + Ps[64][64] = 112 KB
// ---------------------------------------------------------------------------
__global__ __launch_bounds__(256) void attn_kernel(float* __restrict__ out)
{
    extern __shared__ float sm[];
    float* Qs = sm;           // [c][q] 128*64
    float* Ks = sm + 8192;    // [c][k] 128*64
    float* Vs = sm + 16384;   // [j][ch] 64*128
    float* Ps = sm + 24576;   // [r][j] 64*64

    const int tid = threadIdx.x;
    const int tx = tid & 15, ty = tid >> 4;
    const int qtile = blockIdx.x, b = blockIdx.y;
    const int q0 = qtile * 64;

    // load Q tile (channel-major source -> direct, conflict-free)
    #pragma unroll
    for (int p = 0; p < 32; p++) {
        int idx = tid + p * 256;
        Qs[idx] = g_q[(b * C_ + (idx >> 6)) * N_ + q0 + (idx & 63)];
    }

    float O[4][8];
    float m[4], l[4];
    #pragma unroll
    for (int i = 0; i < 4; i++) {
        m[i] = -CUDART_INF_F;
        l[i] = 0.f;
        #pragma unroll
        for (int ch = 0; ch < 8; ch++) O[i][ch] = 0.f;
    }

    for (int kt = 0; kt < 64; kt++) {
        __syncthreads();   // prior PV done with Ks/Vs/Ps
        const int k0 = kt * 64;
        #pragma unroll
        for (int p = 0; p < 32; p++) {
            int idx = tid + p * 256;
            Ks[idx] = g_k[(b * C_ + (idx >> 6)) * N_ + k0 + (idx & 63)];
        }
        #pragma unroll
        for (int p = 0; p < 32; p++) {
            int idx = tid + p * 256;
            Vs[idx] = g_v[(b * N_ + k0 + (idx >> 7)) * C_ + (idx & 127)];
        }
        __syncthreads();

        // S = Q^T K   (per-thread 4x4)
        float s[4][4];
        #pragma unroll
        for (int i = 0; i < 4; i++)
            #pragma unroll
            for (int j = 0; j < 4; j++) s[i][j] = 0.f;

        #pragma unroll 8
        for (int c = 0; c < 128; c++) {
            float4 qf = *(const float4*)&Qs[c * 64 + ty * 4];
            float4 kf = *(const float4*)&Ks[c * 64 + tx * 4];
            s[0][0] += qf.x * kf.x; s[0][1] += qf.x * kf.y;
            s[0][2] += qf.x * kf.z; s[0][3] += qf.x * kf.w;
            s[1][0] += qf.y * kf.x; s[1][1] += qf.y * kf.y;
            s[1][2] += qf.y * kf.z; s[1][3] += qf.y * kf.w;
            s[2][0] += qf.z * kf.x; s[2][1] += qf.z * kf.y;
            s[2][2] += qf.z * kf.z; s[2][3] += qf.z * kf.w;
            s[3][0] += qf.w * kf.x; s[3][1] += qf.w * kf.y;
            s[3][2] += qf.w * kf.z; s[3][3] += qf.w * kf.w;
        }

        // online softmax (16-lane groups share the same 4 rows)
        #pragma unroll
        for (int i = 0; i < 4; i++) {
            float tm = fmaxf(fmaxf(s[i][0], s[i][1]), fmaxf(s[i][2], s[i][3]));
            #pragma unroll
            for (int off = 8; off >= 1; off >>= 1)
                tm = fmaxf(tm, __shfl_xor_sync(0xffffffffu, tm, off, 16));
            float mnew = fmaxf(m[i], tm);
            float corr = __expf(m[i] - mnew);
            l[i] *= corr;
            #pragma unroll
            for (int ch = 0; ch < 8; ch++) O[i][ch] *= corr;
            float rs = 0.f;
            #pragma unroll
            for (int j = 0; j < 4; j++) {
                float p = __expf(s[i][j] - mnew);
                s[i][j] = p;
                rs += p;
            }
            #pragma unroll
            for (int off = 8; off >= 1; off >>= 1)
                rs += __shfl_xor_sync(0xffffffffu, rs, off, 16);
            l[i] += rs;
            m[i] = mnew;
            // P: [r][j], vectorized write
            *(float4*)&Ps[(ty * 4 + i) * 64 + tx * 4] =
                make_float4(s[i][0], s[i][1], s[i][2], s[i][3]);
        }
        __syncthreads();

        // O += P V  (P rows loaded as float4 across 4 keys)
        #pragma unroll 2
        for (int j4 = 0; j4 < 64; j4 += 4) {
            float4 p0 = *(const float4*)&Ps[(ty * 4 + 0) * 64 + j4];
            float4 p1 = *(const float4*)&Ps[(ty * 4 + 1) * 64 + j4];
            float4 p2 = *(const float4*)&Ps[(ty * 4 + 2) * 64 + j4];
            float4 p3 = *(const float4*)&Ps[(ty * 4 + 3) * 64 + j4];
            #pragma unroll
            for (int jj = 0; jj < 4; jj++) {
                float4 v0 = *(const float4*)&Vs[(j4 + jj) * 128 + tx * 8];
                float4 v1 = *(const float4*)&Vs[(j4 + jj) * 128 + tx * 8 + 4];
                float pp0 = (jj == 0) ? p0.x : (jj == 1) ? p0.y : (jj == 2) ? p0.z : p0.w;
                float pp1 = (jj == 0) ? p1.x : (jj == 1) ? p1.y : (jj == 2) ? p1.z : p1.w;
                float pp2 = (jj == 0) ? p2.x : (jj == 1) ? p2.y : (jj == 2) ? p2.z : p2.w;
                float pp3 = (jj == 0) ? p3.x : (jj == 1) ? p3.y : (jj == 2) ? p3.z : p3.w;
                O[0][0] += pp0 * v0.x; O[0][1] += pp0 * v0.y;
                O[0][2] += pp0 * v0.z; O[0][3] += pp0 * v0.w;
                O[0][4] += pp0 * v1.x; O[0][5] += pp0 * v1.y;
                O[0][6] += pp0 * v1.z; O[0][7] += pp0 * v1.w;
                O[1][0] += pp1 * v0.x; O[1][1] += pp1 * v0.y;
                O[1][2] += pp1 * v0.z; O[1][3] += pp1 * v0.w;
                O[1][4] += pp1 * v1.x; O[1][5] += pp1 * v1.y;
                O[1][6] += pp1 * v1.z; O[1][7] += pp1 * v1.w;
                O[2][0] += pp2 * v0.x; O[2][1] += pp2 * v0.y;
                O[2][2] += pp2 * v0.z; O[2][3] += pp2 * v0.w;
                O[2][4] += pp2 * v1.x; O[2][5] += pp2 * v1.y;
                O[2][6] += pp2 * v1.z; O[2][7] += pp2 * v1.w;
                O[3][0] += pp3 * v0.x; O[3][1] += pp3 * v0.y;
                O[3][2] += pp3 * v0.z; O[3][3] += pp3 * v0.w;
                O[3][4] += pp3 * v1.x; O[3][5] += pp3 * v1.y;
                O[3][6] += pp3 * v1.z; O[3][7] += pp3 * v1.w;
            }
        }
    }

    // normalize
    #pragma unroll
    for (int i = 0; i < 4; i++) {
        float inv = 1.f / l[i];
        #pragma unroll
        for (int ch = 0; ch < 8; ch++) O[i][ch] *= inv;
    }

    // transpose through smem for coalesced channel-major store
    __syncthreads();
    float* Os = sm;   // [ch][q] pitch 65 -> 128*65 = 8320 floats (fits in Qs+Ks)
    #pragma unroll
    for (int cc = 0; cc < 8; cc++) {
        int ch = tx * 8 + cc;
        #pragma unroll
        for (int i = 0; i < 4; i++)
            Os[ch * 65 + ty * 4 + i] = O[i][cc];
    }
    __syncthreads();
    #pragma unroll
    for (int p = 0; p < 32; p++) {
        int idx = tid + p * 256;
        int ch = idx >> 6, qq = idx & 63;
        out[(b * C_ + ch) * N_ + q0 + qq] = Os[ch * 65 + qq];
    }
}

// ---------------------------------------------------------------------------
extern "C" void kernel_launch(void* const* d_in, const int* in_sizes, int n_in,
                              void* d_out, int out_size)
{
    const float* x  = (const float*)d_in[0];
    const float* wq = (const float*)d_in[1];
    const float* bq = (const float*)d_in[2];
    const float* wk = (const float*)d_in[3];
    const float* bk = (const float*)d_in[4];
    const float* wv = (const float*)d_in[5];
    const float* bv = (const float*)d_in[6];
    float* out = (float*)d_out;

    cudaFuncSetAttribute(qkv_kernel,
                         cudaFuncAttributeMaxDynamicSharedMemorySize, 65536);
    cudaFuncSetAttribute(attn_kernel,
                         cudaFuncAttributeMaxDynamicSharedMemorySize, 114688);

    qkv_kernel<<<dim3(64, 6, 4), 256, 65536>>>(x, wq, bq, wk, bk, wv, bv);
    attn_kernel<<<dim3(64, 4), 256, 114688>>>(out);
}

// round 4
// speedup vs baseline: 3.7364x; 3.7364x over previous
#include <cuda_runtime.h>
#include <cuda_bf16.h>
#include <math_constants.h>
#include <cstdint>

#define B_ 4
#define C_ 128
#define N_ 4096
#define TQ 128           // queries per CTA
#define TK 64            // keys per iteration
#define NT (N_ / TK)     // 64 iterations

// bf16 hi/lo scratch, all token-major [B][N][C]
__device__ __nv_bfloat16 g_qh[B_*N_*C_], g_ql[B_*N_*C_];
__device__ __nv_bfloat16 g_kh[B_*N_*C_], g_kl[B_*N_*C_];
__device__ __nv_bfloat16 g_vh[B_*N_*C_], g_vl[B_*N_*C_];

// ---------------- helpers ----------------
__device__ __forceinline__ uint32_t smem_u32(const void* p) {
    uint32_t a;
    asm("{ .reg .u64 t; cvta.to.shared.u64 t, %1; cvt.u32.u64 %0, t; }"
        : "=r"(a) : "l"(p));
    return a;
}
__device__ __forceinline__ void cpa16(uint32_t dst, const void* src) {
    asm volatile("cp.async.cg.shared.global [%0], [%1], 16;" :: "r"(dst), "l"(src));
}
__device__ __forceinline__ void cpa_commit() {
    asm volatile("cp.async.commit_group;" ::: "memory");
}
template<int NG> __device__ __forceinline__ void cpa_wait() {
    asm volatile("cp.async.wait_group %0;" :: "n"(NG) : "memory");
}
__device__ __forceinline__ void ldsm4(uint32_t* r, uint32_t a) {
    asm volatile("ldmatrix.sync.aligned.m8n8.x4.shared.b16 {%0,%1,%2,%3}, [%4];"
                 : "=r"(r[0]), "=r"(r[1]), "=r"(r[2]), "=r"(r[3]) : "r"(a));
}
__device__ __forceinline__ void ldsm2(uint32_t* r, uint32_t a) {
    asm volatile("ldmatrix.sync.aligned.m8n8.x2.shared.b16 {%0,%1}, [%2];"
                 : "=r"(r[0]), "=r"(r[1]) : "r"(a));
}
__device__ __forceinline__ void ldsm2t(uint32_t* r, uint32_t a) {
    asm volatile("ldmatrix.sync.aligned.m8n8.x2.trans.shared.b16 {%0,%1}, [%2];"
                 : "=r"(r[0]), "=r"(r[1]) : "r"(a));
}
__device__ __forceinline__ void mma16816(float* d, const uint32_t* a,
                                         const uint32_t* b) {
    asm volatile(
        "mma.sync.aligned.m16n8k16.row.col.f32.bf16.bf16.f32 "
        "{%0,%1,%2,%3}, {%4,%5,%6,%7}, {%8,%9}, {%0,%1,%2,%3};"
        : "+f"(d[0]), "+f"(d[1]), "+f"(d[2]), "+f"(d[3])
        : "r"(a[0]), "r"(a[1]), "r"(a[2]), "r"(a[3]), "r"(b[0]), "r"(b[1]));
}
__device__ __forceinline__ uint32_t pack_bf16(float lo, float hi) {
    // reg low 16 bits = lo (element 0 / col c), high = hi (col c+1)
    uint32_t ul = (uint32_t)__bfloat16_as_ushort(__float2bfloat16_rn(lo));
    uint32_t uh = (uint32_t)__bfloat16_as_ushort(__float2bfloat16_rn(hi));
    return (uh << 16) | ul;
}
// smem row = 256 B (128 bf16). 16B-chunk XOR swizzle: conflict-free ldmatrix.
__device__ __forceinline__ uint32_t swadr(uint32_t base, int row, int chunk) {
    return base + row * 256 + ((chunk ^ (row & 7)) << 4);
}

// SMEM layout (bytes):
// QH 0..32K, QL 32K..64K
// stage s (s=0,1) at 64K + s*64K: KH +0, KL +16K, VH +32K, VL +48K
#define OFF_Q    0
#define OFF_KV   65536
#define STAGE_SZ 65536
#define SMEM_ATTN 196608

// ---------------------------------------------------------------------------
// QKV projection (fp32 SIMT GEMM) -> bf16 hi/lo token-major [B][N][C]
// ---------------------------------------------------------------------------
__global__ __launch_bounds__(256) void qkv_kernel(
    const float* __restrict__ x,
    const float* __restrict__ wq, const float* __restrict__ bq,
    const float* __restrict__ wk, const float* __restrict__ bk,
    const float* __restrict__ wv, const float* __restrict__ bv)
{
    extern __shared__ float sm[];
    float* Xs = sm;          // 128*64
    float* Ws = sm + 8192;   // 64*128

    const int tid = threadIdx.x;
    const int tx = tid & 15, ty = tid >> 4;
    const int ntile = blockIdx.x, otile = blockIdx.y, b = blockIdx.z;

    const float* w; const float* bias;
    __nv_bfloat16 *oh, *ol;
    if (otile < 2)      { w = wq; bias = bq; oh = g_qh; ol = g_ql; }
    else if (otile < 4) { w = wk; bias = bk; oh = g_kh; ol = g_kl; }
    else                { w = wv; bias = bv; oh = g_vh; ol = g_vl; }
    const int orow0 = (otile & 1) * 64;
    const int n0 = ntile * 64;

    #pragma unroll
    for (int p = 0; p < 32; p++) {
        int idx = tid + p * 256;
        Ws[idx] = w[(orow0 + (idx >> 7)) * C_ + (idx & 127)];
    }
    #pragma unroll
    for (int p = 0; p < 32; p++) {
        int idx = tid + p * 256;
        Xs[idx] = x[(b * C_ + (idx >> 6)) * N_ + n0 + (idx & 63)];
    }
    __syncthreads();

    float acc[4][4];
    #pragma unroll
    for (int i = 0; i < 4; i++)
        #pragma unroll
        for (int j = 0; j < 4; j++) acc[i][j] = 0.f;

    #pragma unroll 8
    for (int c = 0; c < 128; c++) {
        float4 xf = *(const float4*)&Xs[c * 64 + tx * 4];
        #pragma unroll
        for (int i = 0; i < 4; i++) {
            float wf = Ws[(ty * 4 + i) * 128 + c];
            acc[i][0] += wf * xf.x; acc[i][1] += wf * xf.y;
            acc[i][2] += wf * xf.z; acc[i][3] += wf * xf.w;
        }
    }

    float bb[4];
    #pragma unroll
    for (int i = 0; i < 4; i++) bb[i] = bias[orow0 + ty * 4 + i];

    // token-major write: 4 consecutive channels per store
    #pragma unroll
    for (int j = 0; j < 4; j++) {
        int n = n0 + tx * 4 + j;
        __nv_bfloat16 h[4], l[4];
        #pragma unroll
        for (int i = 0; i < 4; i++) {
            float v = acc[i][j] + bb[i];
            h[i] = __float2bfloat16_rn(v);
            l[i] = __float2bfloat16_rn(v - __bfloat162float(h[i]));
        }
        size_t base = (size_t)(b * N_ + n) * C_ + orow0 + ty * 4;
        *(uint2*)&oh[base] = *(uint2*)h;
        *(uint2*)&ol[base] = *(uint2*)l;
    }
}

// ---------------------------------------------------------------------------
// mma.sync flash attention, bf16x3. Grid (N/128, B), 256 threads (8 warps).
// Warp w owns query rows [w*16, w*16+16).
// ---------------------------------------------------------------------------
__global__ __launch_bounds__(256, 1) void attn_kernel(float* __restrict__ out)
{
    extern __shared__ char smem[];
    const uint32_t sb = smem_u32(smem);
    const int tid = threadIdx.x;
    const int w = tid >> 5, lane = tid & 31;
    const int b = blockIdx.y;
    const int q0 = blockIdx.x * TQ;

    const uint32_t sbQH = sb + OFF_Q;
    const uint32_t sbQL = sbQH + 32768;

    // ---- prologue: Q (hi/lo) + stage 0 (K,V hi/lo of tile 0) ----
    #pragma unroll
    for (int i = 0; i < 8; i++) {
        int idx = tid + i * 256;              // 2048 chunks
        int row = idx >> 4, ch = idx & 15;
        uint32_t dst = swadr(sbQH, row, ch);
        size_t g = ((size_t)(b * N_ + q0 + row) * C_) * 2 + ch * 16;
        cpa16(dst, (const char*)g_qh + g);
        cpa16(dst + 32768, (const char*)g_ql + g);
    }
    {
        const uint32_t st = sb + OFF_KV;
        #pragma unroll
        for (int i = 0; i < 4; i++) {
            int idx = tid + i * 256;          // 1024 chunks (64 rows x 16)
            int row = idx >> 4, ch = idx & 15;
            uint32_t dst = swadr(st, row, ch);
            size_t g = ((size_t)(b * N_ + row) * C_) * 2 + ch * 16;
            cpa16(dst,         (const char*)g_kh + g);
            cpa16(dst + 16384, (const char*)g_kl + g);
            cpa16(dst + 32768, (const char*)g_vh + g);
            cpa16(dst + 49152, (const char*)g_vl + g);
        }
    }
    cpa_commit();

    float oacc[16][4];
    #pragma unroll
    for (int n = 0; n < 16; n++)
        #pragma unroll
        for (int c = 0; c < 4; c++) oacc[n][c] = 0.f;
    float m0r0 = 0.f, m0r1 = 0.f, lr0 = 0.f, lr1 = 0.f;

    #pragma unroll 1
    for (int t = 0; t < NT; t++) {
        const uint32_t st = sb + OFF_KV + (t & 1) * STAGE_SZ;

        if (t + 1 < NT) {
            const uint32_t nst = sb + OFF_KV + ((t + 1) & 1) * STAGE_SZ;
            const int k0 = (t + 1) * TK;
            #pragma unroll
            for (int i = 0; i < 4; i++) {
                int idx = tid + i * 256;
                int row = idx >> 4, ch = idx & 15;
                uint32_t dst = swadr(nst, row, ch);
                size_t g = ((size_t)(b * N_ + k0 + row) * C_) * 2 + ch * 16;
                cpa16(dst,         (const char*)g_kh + g);
                cpa16(dst + 16384, (const char*)g_kl + g);
                cpa16(dst + 32768, (const char*)g_vh + g);
                cpa16(dst + 49152, (const char*)g_vl + g);
            }
            cpa_commit();
            cpa_wait<1>();
        } else {
            cpa_wait<0>();
        }
        __syncthreads();

        // ---- S = Q Kt^T, bf16x3, per-warp 16x64 ----
        float sacc[8][4];
        #pragma unroll
        for (int n = 0; n < 8; n++)
            #pragma unroll
            for (int c = 0; c < 4; c++) sacc[n][c] = 0.f;

        #pragma unroll
        for (int ks = 0; ks < 8; ks++) {
            uint32_t qh4[4], ql4[4];
            int qrow = w * 16 + (lane & 15);
            int qch = ks * 2 + (lane >> 4);
            uint32_t qa = swadr(sbQH, qrow, qch);
            ldsm4(qh4, qa);
            ldsm4(ql4, qa + 32768);
            #pragma unroll
            for (int nn = 0; nn < 8; nn++) {
                uint32_t kh2[2], kl2[2];
                int krow = nn * 8 + (lane & 7);
                int kch = ks * 2 + ((lane >> 3) & 1);
                uint32_t ka = swadr(st, krow, kch);
                ldsm2(kh2, ka);
                ldsm2(kl2, ka + 16384);
                mma16816(sacc[nn], qh4, kh2);
                mma16816(sacc[nn], qh4, kl2);
                mma16816(sacc[nn], ql4, kh2);
            }
        }

        // ---- softmax with fixed m0 (from tile 0) ----
        if (t == 0) {
            float mx0 = -CUDART_INF_F, mx1 = -CUDART_INF_F;
            #pragma unroll
            for (int n = 0; n < 8; n++) {
                mx0 = fmaxf(mx0, fmaxf(sacc[n][0], sacc[n][1]));
                mx1 = fmaxf(mx1, fmaxf(sacc[n][2], sacc[n][3]));
            }
            #pragma unroll
            for (int off = 1; off <= 2; off <<= 1) {
                mx0 = fmaxf(mx0, __shfl_xor_sync(0xffffffffu, mx0, off));
                mx1 = fmaxf(mx1, __shfl_xor_sync(0xffffffffu, mx1, off));
            }
            m0r0 = mx0; m0r1 = mx1;
        }

        uint32_t ph[4][4], pl[4][4];
        #pragma unroll
        for (int n = 0; n < 8; n++) {
            float p0 = __expf(sacc[n][0] - m0r0);
            float p1 = __expf(sacc[n][1] - m0r0);
            float p2 = __expf(sacc[n][2] - m0r1);
            float p3 = __expf(sacc[n][3] - m0r1);
            lr0 += p0 + p1; lr1 += p2 + p3;
            uint32_t h01 = pack_bf16(p0, p1);
            uint32_t h23 = pack_bf16(p2, p3);
            float h0 = __bfloat162float(__ushort_as_bfloat16((unsigned short)(h01 & 0xffff)));
            float h1 = __bfloat162float(__ushort_as_bfloat16((unsigned short)(h01 >> 16)));
            float h2 = __bfloat162float(__ushort_as_bfloat16((unsigned short)(h23 & 0xffff)));
            float h3 = __bfloat162float(__ushort_as_bfloat16((unsigned short)(h23 >> 16)));
            uint32_t l01 = pack_bf16(p0 - h0, p1 - h1);
            uint32_t l23 = pack_bf16(p2 - h2, p3 - h3);
            int pt = n >> 1, hi = (n & 1) * 2;   // A-frag: regs 0,1 = tile even; 2,3 = tile odd
            ph[pt][hi] = h01; ph[pt][hi + 1] = h23;
            pl[pt][hi] = l01; pl[pt][hi + 1] = l23;
        }

        // ---- O += P V, bf16x3 ----
        const uint32_t vst = st + 32768;
        #pragma unroll
        for (int kk = 0; kk < 4; kk++) {
            int vrow = kk * 16 + (lane & 15);
            #pragma unroll
            for (int nn = 0; nn < 16; nn++) {
                uint32_t bh[2], bl[2];
                uint32_t va = swadr(vst, vrow, nn);
                ldsm2t(bh, va);
                ldsm2t(bl, va + 16384);
                mma16816(oacc[nn], ph[kk], bh);
                mma16816(oacc[nn], ph[kk], bl);
                mma16816(oacc[nn], pl[kk], bh);
            }
        }
        __syncthreads();
    }

    // ---- epilogue: reduce l across quad, normalize, store ----
    #pragma unroll
    for (int off = 1; off <= 2; off <<= 1) {
        lr0 += __shfl_xor_sync(0xffffffffu, lr0, off);
        lr1 += __shfl_xor_sync(0xffffffffu, lr1, off);
    }
    float inv0 = 1.f / lr0, inv1 = 1.f / lr1;
    int qa = q0 + w * 16 + (lane >> 2);
    #pragma unroll
    for (int nn = 0; nn < 16; nn++) {
        int ch = nn * 8 + (lane & 3) * 2;
        out[((size_t)b * C_ + ch) * N_ + qa]           = oacc[nn][0] * inv0;
        out[((size_t)b * C_ + ch + 1) * N_ + qa]       = oacc[nn][1] * inv0;
        out[((size_t)b * C_ + ch) * N_ + qa + 8]       = oacc[nn][2] * inv1;
        out[((size_t)b * C_ + ch + 1) * N_ + qa + 8]   = oacc[nn][3] * inv1;
    }
}

// ---------------------------------------------------------------------------
extern "C" void kernel_launch(void* const* d_in, const int* in_sizes, int n_in,
                              void* d_out, int out_size)
{
    const float* x  = (const float*)d_in[0];
    const float* wq = (const float*)d_in[1];
    const float* bq = (const float*)d_in[2];
    const float* wk = (const float*)d_in[3];
    const float* bk = (const float*)d_in[4];
    const float* wv = (const float*)d_in[5];
    const float* bv = (const float*)d_in[6];
    float* out = (float*)d_out;

    cudaFuncSetAttribute(qkv_kernel,
                         cudaFuncAttributeMaxDynamicSharedMemorySize, 65536);
    cudaFuncSetAttribute(attn_kernel,
                         cudaFuncAttributeMaxDynamicSharedMemorySize, SMEM_ATTN);

    qkv_kernel<<<dim3(64, 6, 4), 256, 65536>>>(x, wq, bq, wk, bk, wv, bv);
    attn_kernel<<<dim3(N_ / TQ, B_), 256, SMEM_ATTN>>>(out);
}

// round 5
// speedup vs baseline: 3.8313x; 1.0254x over previous
#include <cuda_runtime.h>
#include <cuda_bf16.h>
#include <math_constants.h>
#include <cstdint>

#define B_ 4
#define C_ 128
#define N_ 4096
#define TQ 128           // queries per CTA
#define TK 64            // keys per iteration
#define NT (N_ / TK)     // 64 iterations

// bf16 hi/lo scratch, all token-major [B][N][C]
__device__ __nv_bfloat16 g_qh[B_*N_*C_], g_ql[B_*N_*C_];
__device__ __nv_bfloat16 g_kh[B_*N_*C_], g_kl[B_*N_*C_];
__device__ __nv_bfloat16 g_vh[B_*N_*C_], g_vl[B_*N_*C_];

// ---------------- helpers ----------------
__device__ __forceinline__ uint32_t smem_u32(const void* p) {
    uint32_t a;
    asm("{ .reg .u64 t; cvta.to.shared.u64 t, %1; cvt.u32.u64 %0, t; }"
        : "=r"(a) : "l"(p));
    return a;
}
__device__ __forceinline__ void cpa16(uint32_t dst, const void* src) {
    asm volatile("cp.async.cg.shared.global [%0], [%1], 16;" :: "r"(dst), "l"(src));
}
__device__ __forceinline__ void cpa_commit() {
    asm volatile("cp.async.commit_group;" ::: "memory");
}
template<int NG> __device__ __forceinline__ void cpa_wait() {
    asm volatile("cp.async.wait_group %0;" :: "n"(NG) : "memory");
}
__device__ __forceinline__ void ldsm4(uint32_t* r, uint32_t a) {
    asm volatile("ldmatrix.sync.aligned.m8n8.x4.shared.b16 {%0,%1,%2,%3}, [%4];"
                 : "=r"(r[0]), "=r"(r[1]), "=r"(r[2]), "=r"(r[3]) : "r"(a));
}
__device__ __forceinline__ void ldsm4t(uint32_t* r, uint32_t a) {
    asm volatile("ldmatrix.sync.aligned.m8n8.x4.trans.shared.b16 {%0,%1,%2,%3}, [%4];"
                 : "=r"(r[0]), "=r"(r[1]), "=r"(r[2]), "=r"(r[3]) : "r"(a));
}
__device__ __forceinline__ void mma16816(float* d, const uint32_t* a,
                                         const uint32_t* b) {
    asm volatile(
        "mma.sync.aligned.m16n8k16.row.col.f32.bf16.bf16.f32 "
        "{%0,%1,%2,%3}, {%4,%5,%6,%7}, {%8,%9}, {%0,%1,%2,%3};"
        : "+f"(d[0]), "+f"(d[1]), "+f"(d[2]), "+f"(d[3])
        : "r"(a[0]), "r"(a[1]), "r"(a[2]), "r"(a[3]), "r"(b[0]), "r"(b[1]));
}
__device__ __forceinline__ uint32_t pack_bf16(float lo, float hi) {
    uint32_t ul = (uint32_t)__bfloat16_as_ushort(__float2bfloat16_rn(lo));
    uint32_t uh = (uint32_t)__bfloat16_as_ushort(__float2bfloat16_rn(hi));
    return (uh << 16) | ul;
}
// smem row = 256 B (128 bf16). 16B-chunk XOR swizzle: conflict-free ldmatrix.
__device__ __forceinline__ uint32_t swadr(uint32_t base, int row, int chunk) {
    return base + row * 256 + ((chunk ^ (row & 7)) << 4);
}

// SMEM layout (bytes):
// QH 0..32K, QL 32K..64K
// stage s (s=0,1) at 64K + s*64K: KH +0, KL +16K, VH +32K, VL +48K
#define OFF_Q    0
#define OFF_KV   65536
#define STAGE_SZ 65536
#define SMEM_ATTN 196608

// ---------------------------------------------------------------------------
// QKV projection (fp32 SIMT GEMM) -> bf16 hi/lo token-major [B][N][C]
// ---------------------------------------------------------------------------
__global__ __launch_bounds__(256) void qkv_kernel(
    const float* __restrict__ x,
    const float* __restrict__ wq, const float* __restrict__ bq,
    const float* __restrict__ wk, const float* __restrict__ bk,
    const float* __restrict__ wv, const float* __restrict__ bv)
{
    extern __shared__ float sm[];
    float* Xs = sm;          // 128*64
    float* Ws = sm + 8192;   // 64*128

    const int tid = threadIdx.x;
    const int tx = tid & 15, ty = tid >> 4;
    const int ntile = blockIdx.x, otile = blockIdx.y, b = blockIdx.z;

    const float* w; const float* bias;
    __nv_bfloat16 *oh, *ol;
    if (otile < 2)      { w = wq; bias = bq; oh = g_qh; ol = g_ql; }
    else if (otile < 4) { w = wk; bias = bk; oh = g_kh; ol = g_kl; }
    else                { w = wv; bias = bv; oh = g_vh; ol = g_vl; }
    const int orow0 = (otile & 1) * 64;
    const int n0 = ntile * 64;

    #pragma unroll
    for (int p = 0; p < 32; p++) {
        int idx = tid + p * 256;
        Ws[idx] = w[(orow0 + (idx >> 7)) * C_ + (idx & 127)];
    }
    #pragma unroll
    for (int p = 0; p < 32; p++) {
        int idx = tid + p * 256;
        Xs[idx] = x[(b * C_ + (idx >> 6)) * N_ + n0 + (idx & 63)];
    }
    __syncthreads();

    float acc[4][4];
    #pragma unroll
    for (int i = 0; i < 4; i++)
        #pragma unroll
        for (int j = 0; j < 4; j++) acc[i][j] = 0.f;

    #pragma unroll 8
    for (int c = 0; c < 128; c++) {
        float4 xf = *(const float4*)&Xs[c * 64 + tx * 4];
        #pragma unroll
        for (int i = 0; i < 4; i++) {
            float wf = Ws[(ty * 4 + i) * 128 + c];
            acc[i][0] += wf * xf.x; acc[i][1] += wf * xf.y;
            acc[i][2] += wf * xf.z; acc[i][3] += wf * xf.w;
        }
    }

    float bb[4];
    #pragma unroll
    for (int i = 0; i < 4; i++) bb[i] = bias[orow0 + ty * 4 + i];

    #pragma unroll
    for (int j = 0; j < 4; j++) {
        int n = n0 + tx * 4 + j;
        __nv_bfloat16 h[4], l[4];
        #pragma unroll
        for (int i = 0; i < 4; i++) {
            float v = acc[i][j] + bb[i];
            h[i] = __float2bfloat16_rn(v);
            l[i] = __float2bfloat16_rn(v - __bfloat162float(h[i]));
        }
        size_t base = (size_t)(b * N_ + n) * C_ + orow0 + ty * 4;
        *(uint2*)&oh[base] = *(uint2*)h;
        *(uint2*)&ol[base] = *(uint2*)l;
    }
}

// ---------------------------------------------------------------------------
// mma.sync flash attention, bf16x3, softmax fused into PV loop.
// Grid (N/128, B), 256 threads (8 warps). Warp w owns query rows [w*16, w*16+16).
// ---------------------------------------------------------------------------
__global__ __launch_bounds__(256, 1) void attn_kernel(float* __restrict__ out)
{
    extern __shared__ char smem[];
    const uint32_t sb = smem_u32(smem);
    const int tid = threadIdx.x;
    const int w = tid >> 5, lane = tid & 31;
    const int b = blockIdx.y;
    const int q0 = blockIdx.x * TQ;

    const uint32_t sbQH = sb + OFF_Q;

    // ---- prologue: Q (hi/lo) + stage 0 (K,V hi/lo of tile 0) ----
    #pragma unroll
    for (int i = 0; i < 8; i++) {
        int idx = tid + i * 256;              // 2048 chunks
        int row = idx >> 4, ch = idx & 15;
        uint32_t dst = swadr(sbQH, row, ch);
        size_t g = ((size_t)(b * N_ + q0 + row) * C_) * 2 + ch * 16;
        cpa16(dst, (const char*)g_qh + g);
        cpa16(dst + 32768, (const char*)g_ql + g);
    }
    {
        const uint32_t st = sb + OFF_KV;
        #pragma unroll
        for (int i = 0; i < 4; i++) {
            int idx = tid + i * 256;          // 1024 chunks (64 rows x 16)
            int row = idx >> 4, ch = idx & 15;
            uint32_t dst = swadr(st, row, ch);
            size_t g = ((size_t)(b * N_ + row) * C_) * 2 + ch * 16;
            cpa16(dst,         (const char*)g_kh + g);
            cpa16(dst + 16384, (const char*)g_kl + g);
            cpa16(dst + 32768, (const char*)g_vh + g);
            cpa16(dst + 49152, (const char*)g_vl + g);
        }
    }
    cpa_commit();

    float oacc[16][4];
    #pragma unroll
    for (int n = 0; n < 16; n++)
        #pragma unroll
        for (int c = 0; c < 4; c++) oacc[n][c] = 0.f;
    float m0r0 = 0.f, m0r1 = 0.f, lr0 = 0.f, lr1 = 0.f;

    #pragma unroll 1
    for (int t = 0; t < NT; t++) {
        const uint32_t st = sb + OFF_KV + (t & 1) * STAGE_SZ;

        if (t + 1 < NT) {
            const uint32_t nst = sb + OFF_KV + ((t + 1) & 1) * STAGE_SZ;
            const int k0 = (t + 1) * TK;
            #pragma unroll
            for (int i = 0; i < 4; i++) {
                int idx = tid + i * 256;
                int row = idx >> 4, ch = idx & 15;
                uint32_t dst = swadr(nst, row, ch);
                size_t g = ((size_t)(b * N_ + k0 + row) * C_) * 2 + ch * 16;
                cpa16(dst,         (const char*)g_kh + g);
                cpa16(dst + 16384, (const char*)g_kl + g);
                cpa16(dst + 32768, (const char*)g_vh + g);
                cpa16(dst + 49152, (const char*)g_vl + g);
            }
            cpa_commit();
            cpa_wait<1>();
        } else {
            cpa_wait<0>();
        }
        __syncthreads();

        // ---- S = Q Kt^T, bf16x3, per-warp 16x64 ----
        float sacc[8][4];
        #pragma unroll
        for (int n = 0; n < 8; n++)
            #pragma unroll
            for (int c = 0; c < 4; c++) sacc[n][c] = 0.f;

        #pragma unroll
        for (int ks = 0; ks < 8; ks++) {
            uint32_t qh4[4], ql4[4];
            int qrow = w * 16 + (lane & 15);
            int qch = ks * 2 + (lane >> 4);
            uint32_t qa = swadr(sbQH, qrow, qch);
            ldsm4(qh4, qa);
            ldsm4(ql4, qa + 32768);
            #pragma unroll
            for (int np = 0; np < 4; np++) {
                // paired K load: n-tiles 2np, 2np+1 in one ldsm4
                uint32_t khp[4], klp[4];
                int krow = (2 * np + (lane >> 4)) * 8 + (lane & 7);
                int kch = ks * 2 + ((lane >> 3) & 1);
                uint32_t ka = swadr(st, krow, kch);
                ldsm4(khp, ka);
                ldsm4(klp, ka + 16384);
                mma16816(sacc[2*np],   qh4, khp);
                mma16816(sacc[2*np+1], qh4, khp + 2);
                mma16816(sacc[2*np],   qh4, klp);
                mma16816(sacc[2*np+1], qh4, klp + 2);
                mma16816(sacc[2*np],   ql4, khp);
                mma16816(sacc[2*np+1], ql4, khp + 2);
            }
        }

        // ---- fixed m0 from tile 0 ----
        if (t == 0) {
            float mx0 = -CUDART_INF_F, mx1 = -CUDART_INF_F;
            #pragma unroll
            for (int n = 0; n < 8; n++) {
                mx0 = fmaxf(mx0, fmaxf(sacc[n][0], sacc[n][1]));
                mx1 = fmaxf(mx1, fmaxf(sacc[n][2], sacc[n][3]));
            }
            #pragma unroll
            for (int off = 1; off <= 2; off <<= 1) {
                mx0 = fmaxf(mx0, __shfl_xor_sync(0xffffffffu, mx0, off));
                mx1 = fmaxf(mx1, __shfl_xor_sync(0xffffffffu, mx1, off));
            }
            m0r0 = mx0; m0r1 = mx1;
        }

        // ---- fused softmax + PV per 16-key chunk ----
        const uint32_t vst = st + 32768;
        #pragma unroll
        for (int kk = 0; kk < 4; kk++) {
            uint32_t ph[4], pl[4];
            #pragma unroll
            for (int half = 0; half < 2; half++) {
                int n = 2 * kk + half;
                float p0 = __expf(sacc[n][0] - m0r0);
                float p1 = __expf(sacc[n][1] - m0r0);
                float p2 = __expf(sacc[n][2] - m0r1);
                float p3 = __expf(sacc[n][3] - m0r1);
                lr0 += p0 + p1; lr1 += p2 + p3;
                uint32_t h01 = pack_bf16(p0, p1);
                uint32_t h23 = pack_bf16(p2, p3);
                float h0 = __bfloat162float(__ushort_as_bfloat16((unsigned short)(h01 & 0xffff)));
                float h1 = __bfloat162float(__ushort_as_bfloat16((unsigned short)(h01 >> 16)));
                float h2 = __bfloat162float(__ushort_as_bfloat16((unsigned short)(h23 & 0xffff)));
                float h3 = __bfloat162float(__ushort_as_bfloat16((unsigned short)(h23 >> 16)));
                ph[half * 2]     = h01;
                ph[half * 2 + 1] = h23;
                pl[half * 2]     = pack_bf16(p0 - h0, p1 - h1);
                pl[half * 2 + 1] = pack_bf16(p2 - h2, p3 - h3);
            }
            #pragma unroll
            for (int np = 0; np < 8; np++) {
                // paired V load: channel groups 2np, 2np+1 in one ldsm4t
                uint32_t vh[4], vl[4];
                uint32_t va = swadr(vst, kk * 16 + (lane & 15), 2 * np + (lane >> 4));
                ldsm4t(vh, va);
                ldsm4t(vl, va + 16384);
                mma16816(oacc[2*np],   ph, vh);
                mma16816(oacc[2*np+1], ph, vh + 2);
                mma16816(oacc[2*np],   ph, vl);
                mma16816(oacc[2*np+1], ph, vl + 2);
                mma16816(oacc[2*np],   pl, vh);
                mma16816(oacc[2*np+1], pl, vh + 2);
            }
        }
        __syncthreads();
    }

    // ---- epilogue: reduce l across quad, normalize, store ----
    #pragma unroll
    for (int off = 1; off <= 2; off <<= 1) {
        lr0 += __shfl_xor_sync(0xffffffffu, lr0, off);
        lr1 += __shfl_xor_sync(0xffffffffu, lr1, off);
    }
    float inv0 = 1.f / lr0, inv1 = 1.f / lr1;
    int qa = q0 + w * 16 + (lane >> 2);
    #pragma unroll
    for (int nn = 0; nn < 16; nn++) {
        int ch = nn * 8 + (lane & 3) * 2;
        out[((size_t)b * C_ + ch) * N_ + qa]           = oacc[nn][0] * inv0;
        out[((size_t)b * C_ + ch + 1) * N_ + qa]       = oacc[nn][1] * inv0;
        out[((size_t)b * C_ + ch) * N_ + qa + 8]       = oacc[nn][2] * inv1;
        out[((size_t)b * C_ + ch + 1) * N_ + qa + 8]   = oacc[nn][3] * inv1;
    }
}

// ---------------------------------------------------------------------------
extern "C" void kernel_launch(void* const* d_in, const int* in_sizes, int n_in,
                              void* d_out, int out_size)
{
    const float* x  = (const float*)d_in[0];
    const float* wq = (const float*)d_in[1];
    const float* bq = (const float*)d_in[2];
    const float* wk = (const float*)d_in[3];
    const float* bk = (const float*)d_in[4];
    const float* wv = (const float*)d_in[5];
    const float* bv = (const float*)d_in[6];
    float* out = (float*)d_out;

    cudaFuncSetAttribute(qkv_kernel,
                         cudaFuncAttributeMaxDynamicSharedMemorySize, 65536);
    cudaFuncSetAttribute(attn_kernel,
                         cudaFuncAttributeMaxDynamicSharedMemorySize, SMEM_ATTN);

    qkv_kernel<<<dim3(64, 6, 4), 256, 65536>>>(x, wq, bq, wk, bk, wv, bv);
    attn_kernel<<<dim3(N_ / TQ, B_), 256, SMEM_ATTN>>>(out);
}